// round 11
// baseline (speedup 1.0000x reference)
#include <cuda_runtime.h>
#include <math.h>

#define BATCH   512
#define NSTEPS  20000
#define NTUM    64
#define NCHUNK  125                 // chunks per batch
#define CS      160                 // steps per chunk
#define NGRP    5                   // 32-step groups per chunk
#define NCTOT   (BATCH * NCHUNK)    // 64000 chunks total
#define E0SLEN  ((NTUM + 1) * 3)    // 195 floats per batch

#define K1_WORK_BLOCKS  2000        // 8 warps * 4 chunks = 32 chunks/block
#define K1_FRAME_BLOCKS 64          // 8 warps/block * 64 = 512 frame warps
#define K3_SEGS         16          // 8 chunks per segment (16*8 = 128 >= 125)
#define K3_BLOCKS       (BATCH * K3_SEGS)   // 8192 blocks, 1 chunk per warp

// ---------------- global scratch (L2 resident, ~7 MB) ----------------
__device__ uint4    g_ball4[NCTOT * NGRP];       // 5.12 MB ballots (x=wA1,y=wA2,z=wB0)
__device__ unsigned g_cinfo[NCTOT];              // packed chunk maps
__device__ unsigned g_gmask[NCTOT];              // per-group fast bits
__device__ unsigned g_entry[NCTOT];              // z | C<<1
__device__ float    g_off  [NCTOT * 3];          // chunk base positions
__device__ float    g_e0s  [BATCH * E0SLEN];

// ---------------- small vector helpers ----------------
struct F3 { float x, y, z; };
__device__ __forceinline__ F3 mk3(float x, float y, float z) { F3 r{x, y, z}; return r; }
__device__ __forceinline__ float dot3(F3 a, F3 b) { return a.x * b.x + a.y * b.y + a.z * b.z; }
__device__ __forceinline__ F3 cross3(F3 a, F3 b) {
    return mk3(a.y * b.z - a.z * b.y, a.z * b.x - a.x * b.z, a.x * b.y - a.y * b.x);
}
__device__ __forceinline__ F3 nrm3(F3 v) {
    float r = rsqrtf(v.x * v.x + v.y * v.y + v.z * v.z);
    return mk3(v.x * r, v.y * r, v.z * r);
}
__device__ __forceinline__ F3 ortho3(F3 v, F3 u) {
    float k = __fdividef(dot3(v, u), dot3(u, u));
    return mk3(v.x - k * u.x, v.y - k * u.y, v.z - k * u.z);
}
__device__ __forceinline__ float cauchy_angle(float u, float sig) {
    float a = sig * tanf((float)M_PI * (u - 0.5f));   // mu = 0
    if (!isfinite(a)) a = 0.0f;
    return fmodf(a, (float)M_PI);
}
__device__ __forceinline__ void mm3(float* C, const float* A, const float* B) {
#pragma unroll
    for (int i = 0; i < 3; ++i)
#pragma unroll
        for (int j = 0; j < 3; ++j)
            C[3 * i + j] = A[3 * i + 0] * B[j] + A[3 * i + 1] * B[3 + j] +
                           A[3 * i + 2] * B[6 + j];
}

// ---------------- affine GF(2) prefix over 32 steps ----------------------
__device__ __forceinline__ unsigned affineZ(unsigned wA1, unsigned wA2,
                                            unsigned wB0, unsigned zin) {
    unsigned a = ~(wA1 | wA2);
    unsigned P = a ^ wB0;
    unsigned Q = wB0;
#pragma unroll
    for (int k = 1; k < 32; k <<= 1) {
        Q = Q ^ (P & (Q << k));
        P = P & ((P << k) | ((1u << k) - 1u));
    }
    return Q ^ (zin ? P : 0u);
}

__device__ __forceinline__ int clipIdx(int c) {
    int idx = c - 1;
    return idx < 0 ? 0 : (idx > NTUM ? NTUM : idx);
}

// chunk map: bit0=z_out(entry z=1), bit1=z_out(entry z=0),
// [2,17)=cnt(entry=1), [17,32)=cnt(entry=0). Identity = 1.
__device__ __forceinline__ unsigned composeMap(unsigned m1, unsigned m2) {
    unsigned z1 = m1 & 1u;
    unsigned z0 = (m1 >> 1) & 1u;
    unsigned c2a = (m2 >> 2) & 0x7FFFu;
    unsigned c2b = (m2 >> 17) & 0x7FFFu;
    unsigned o1 = z1 ? (m2 & 1u) : ((m2 >> 1) & 1u);
    unsigned o0 = z0 ? (m2 & 1u) : ((m2 >> 1) & 1u);
    unsigned d1 = ((m1 >> 2) & 0x7FFFu) + (z1 ? c2a : c2b);
    unsigned d0 = ((m1 >> 17) & 0x7FFFu) + (z0 ? c2a : c2b);
    return o1 | (o0 << 1) | (d1 << 2) | (d0 << 17);
}

// ============================================================================
// K1: ballots + chunk maps (full-chip parallel) + frame matrix scan
// ============================================================================
__global__ void __launch_bounds__(256)
k1_ballots(const float* __restrict__ r0, const float* __restrict__ r1,
           const float* __restrict__ v0, const float* __restrict__ v1,
           const float* __restrict__ up, const float* __restrict__ un) {
    const int wid  = threadIdx.x >> 5;
    const int lane = threadIdx.x & 31;
    const unsigned FULL = 0xffffffffu;
    const float R01 = 1e-3f, R10 = 1e-3f;
    const float TH  = (float)(1.0 - 1e-3);

    if (blockIdx.x >= K1_WORK_BLOCKS) {
        // -------- frame warps: one batch per warp, matrix prefix scan ------
        int b = (blockIdx.x - K1_WORK_BLOCKS) * 8 + wid;
        if (b >= BATCH) return;
        int i0 = 2 * lane, i1 = 2 * lane + 1;
        float ap0 = cauchy_angle(up[b * NTUM + i0], 0.1f);
        float an0 = cauchy_angle(un[b * NTUM + i0], 0.5f);
        float ap1 = cauchy_angle(up[b * NTUM + i1], 0.1f);
        float an1 = cauchy_angle(un[b * NTUM + i1], 0.5f);
        float cp0 = cosf(ap0), sp0 = sinf(ap0), cb0 = cosf(an0), sb0 = sinf(an0);
        float cp1 = cosf(ap1), sp1 = sinf(ap1), cb1 = cosf(an1), sb1 = sinf(an1);
        float A[9] = { cp0 * cb0, -sp0, cp0 * sb0,
                       sp0 * cb0,  cp0, sp0 * sb0,
                       -sb0,       0.f, cb0 };
        float L1m[9] = { cp1 * cb1, -sp1, cp1 * sb1,
                         sp1 * cb1,  cp1, sp1 * sb1,
                         -sb1,       0.f, cb1 };
        float P[9];
        mm3(P, A, L1m);
#pragma unroll
        for (int k = 1; k < 32; k <<= 1) {
            float U[9];
#pragma unroll
            for (int q = 0; q < 9; ++q) U[q] = __shfl_up_sync(FULL, P[q], k);
            float T[9];
            mm3(T, U, P);
            if (lane >= k) {
#pragma unroll
                for (int q = 0; q < 9; ++q) P[q] = T[q];
            }
        }
        float E[9];
#pragma unroll
        for (int q = 0; q < 9; ++q) E[q] = __shfl_up_sync(FULL, P[q], 1);
        if (lane == 0) {
            E[0] = 1.f; E[1] = 0.f; E[2] = 0.f;
            E[3] = 0.f; E[4] = 1.f; E[5] = 0.f;
            E[6] = 0.f; E[7] = 0.f; E[8] = 1.f;
        }
        F3 a = mk3(v0[b * 3 + 0], v0[b * 3 + 1], v0[b * 3 + 2]);
        F3 c = mk3(v1[b * 3 + 0], v1[b * 3 + 1], v1[b * 3 + 2]);
        F3 e0 = nrm3(a);
        F3 e1 = nrm3(ortho3(c, e0));
        F3 e2 = nrm3(cross3(e0, e1));
        float* eo = &g_e0s[b * E0SLEN];
        if (lane == 0) { eo[0] = e0.x; eo[1] = e0.y; eo[2] = e0.z; }
        float a0x = A[0], a0y = A[3], a0z = A[6];
        float q1x = E[0] * a0x + E[1] * a0y + E[2] * a0z;
        float q1y = E[3] * a0x + E[4] * a0y + E[5] * a0z;
        float q1z = E[6] * a0x + E[7] * a0y + E[8] * a0z;
        int o1 = (2 * lane + 1) * 3;
        eo[o1 + 0] = q1x * e0.x + q1y * e1.x + q1z * e2.x;
        eo[o1 + 1] = q1x * e0.y + q1y * e1.y + q1z * e2.y;
        eo[o1 + 2] = q1x * e0.z + q1y * e1.z + q1z * e2.z;
        float q2x = P[0], q2y = P[3], q2z = P[6];
        int o2 = (2 * lane + 2) * 3;
        eo[o2 + 0] = q2x * e0.x + q2y * e1.x + q2z * e2.x;
        eo[o2 + 1] = q2x * e0.y + q2y * e1.y + q2z * e2.y;
        eo[o2 + 2] = q2x * e0.z + q2y * e1.z + q2z * e2.z;
        return;
    }

    // -------- worker warps: 4 chunks each, batch-agnostic ------------------
    int wgid = blockIdx.x * 8 + wid;          // 0..15999
#pragma unroll
    for (int j = 0; j < 4; ++j) {
        int c = wgid * 4 + j;                 // 0..63999
        int b = c / NCHUNK;
        int ck = c - b * NCHUNK;
        int base = b * NSTEPS + ck * CS;
        // preload ALL group values first -> 10 outstanding LDGs (MLP)
        float a0v[NGRP], a1v[NGRP];
#pragma unroll
        for (int g = 0; g < NGRP; ++g) a0v[g] = r0[base + g * 32 + lane];
#pragma unroll
        for (int g = 0; g < NGRP; ++g) a1v[g] = r1[base + g * 32 + lane];

        unsigned zA = 1u, zB = 0u;
        unsigned cntA = 0, cntB = 0, gmask = 0;
#pragma unroll
        for (int g = 0; g < NGRP; ++g) {
            unsigned wA1 = __ballot_sync(FULL, a0v[g] < R01);
            unsigned wA2 = __ballot_sync(FULL, a0v[g] > TH);
            unsigned wB0 = __ballot_sync(FULL, a1v[g] < R10);
            bool fast = ((wA1 | wA2 | wB0) == 0u) && !(ck == 0 && g == 0);
            if (fast) { gmask |= 1u << g; continue; }
            if (lane == 0)
                g_ball4[c * NGRP + g] = make_uint4(wA1, wA2, wB0, 0u);  // one STG.128
            unsigned ZA = affineZ(wA1, wA2, wB0, zA);
            unsigned ZB = affineZ(wA1, wA2, wB0, zB);
            unsigned S2A = ((ZA << 1) | zA) & wA2;
            unsigned S2B = ((ZB << 1) | zB) & wA2;
            if (ck == 0 && g == 0) { S2A &= ~1u; S2B &= ~1u; }
            cntA += __popc(S2A);
            cntB += __popc(S2B);
            zA = ZA >> 31;
            zB = ZB >> 31;
        }
        if (lane == 0) {
            g_cinfo[c] = zA | (zB << 1) | (cntA << 2) | (cntB << 17);
            g_gmask[c] = gmask;
        }
    }
}

// ============================================================================
// K2: per-batch scans + chunk sums -> g_entry, g_off
// ============================================================================
__global__ void __launch_bounds__(256)
k2_scan(const float* __restrict__ x0) {
    __shared__ float    s_e0s[E0SLEN];
    __shared__ unsigned s_entry[NCHUNK];
    __shared__ float    s_sx[NCHUNK], s_sy[NCHUNK], s_sz[NCHUNK];

    const int b    = blockIdx.x;
    const int tid  = threadIdx.x;
    const int w    = tid >> 5;
    const int lane = tid & 31;
    const unsigned FULL = 0xffffffffu;
    const unsigned lemask = FULL >> (31 - lane);
    const int cbase = b * NCHUNK;

    // lane-parallel gmask prefetch: lanes 0..15 load one word each (1 trip)
    const int cs = w * 16;
    const int ce = cs + 16 > NCHUNK ? NCHUNK : cs + 16;
    unsigned gmv = 0x1Fu;
    if (lane < 16 && cs + lane < NCHUNK) gmv = g_gmask[cbase + cs + lane];

    for (int i = tid; i < E0SLEN; i += 256)
        s_e0s[i] = g_e0s[b * E0SLEN + i];

    // scan A (warp 0): chunk entry (z, C)
    if (w == 0) {
        unsigned m = 1u;
        int ck0 = lane * 4;
        unsigned mloc[4];
#pragma unroll
        for (int j = 0; j < 4; ++j) {
            int ck = ck0 + j;
            mloc[j] = (ck < NCHUNK) ? g_cinfo[cbase + ck] : 1u;
            m = composeMap(m, mloc[j]);
        }
#pragma unroll
        for (int k = 1; k < 32; k <<= 1) {
            unsigned mu = __shfl_up_sync(FULL, m, k);
            unsigned mc = composeMap(mu, m);
            if (lane >= k) m = mc;
        }
        unsigned ex = __shfl_up_sync(FULL, m, 1);
        if (lane == 0) ex = 1u;
        unsigned z = ex & 1u;
        unsigned C = (ex >> 2) & 0x7FFFu;
#pragma unroll
        for (int j = 0; j < 4; ++j) {
            int ck = ck0 + j;
            if (ck < NCHUNK) {
                unsigned e = z | (C << 1);
                s_entry[ck] = e;
                g_entry[cbase + ck] = e;
                unsigned mm = mloc[j];
                C += z ? ((mm >> 2) & 0x7FFFu) : ((mm >> 17) & 0x7FFFu);
                z = z ? (mm & 1u) : ((mm >> 1) & 1u);
            }
        }
    }
    __syncthreads();

    // chunk sums: warp w handles [cs, ce)
    for (int jj = 0; jj < 16; ++jj) {
        int ck = cs + jj;
        if (ck >= ce) break;
        unsigned e = s_entry[ck];
        unsigned z = e & 1u;
        int Cin = (int)(e >> 1);
        unsigned gm = __shfl_sync(FULL, gmv, jj);
        if (gm == 0x1Fu) {
            if (lane == 0) {
                float spd = z ? 1e-3f : 5e-3f;
                int idx = clipIdx(Cin);
                s_sx[ck] = CS * spd * s_e0s[idx * 3 + 0];
                s_sy[ck] = CS * spd * s_e0s[idx * 3 + 1];
                s_sz[ck] = CS * spd * s_e0s[idx * 3 + 2];
            }
            continue;
        }
        int sofar = 0;
        float ax = 0.f, ay = 0.f, az = 0.f;
        float ux = 0.f, uy = 0.f, uz = 0.f;
#pragma unroll
        for (int g = 0; g < NGRP; ++g) {
            if ((gm >> g) & 1u) {
                float spd = z ? 1e-3f : 5e-3f;
                int idx = clipIdx(Cin + sofar);
                ux += 32.f * spd * s_e0s[idx * 3 + 0];
                uy += 32.f * spd * s_e0s[idx * 3 + 1];
                uz += 32.f * spd * s_e0s[idx * 3 + 2];
                continue;
            }
            uint4 bw = g_ball4[(cbase + ck) * NGRP + g];   // one LDG.128 broadcast
            unsigned wA1 = bw.x, wA2 = bw.y, wB0 = bw.z;
            unsigned Z = affineZ(wA1, wA2, wB0, z);
            unsigned Zp = (Z << 1) | z;
            unsigned S2 = Zp & wA2;
            unsigned S1 = (Zp & wA1) | (~Zp & ~wB0);
            if (ck == 0 && g == 0) S2 &= ~1u;
            int c = Cin + sofar + __popc(S2 & lemask);
            sofar += __popc(S2);
            z = Z >> 31;
            bool tum = (S2 >> lane) & 1u;
            if (ck == 0 && g == 0 && lane == 0) {
                ax += x0[b * 3 + 0]; ay += x0[b * 3 + 1]; az += x0[b * 3 + 2];
            } else if (!tum) {
                float spd = ((S1 >> lane) & 1u) ? 5e-3f : 1e-3f;
                int idx = clipIdx(c);
                ax += spd * s_e0s[idx * 3 + 0];
                ay += spd * s_e0s[idx * 3 + 1];
                az += spd * s_e0s[idx * 3 + 2];
            }
        }
#pragma unroll
        for (int o = 16; o; o >>= 1) {
            ax += __shfl_xor_sync(FULL, ax, o);
            ay += __shfl_xor_sync(FULL, ay, o);
            az += __shfl_xor_sync(FULL, az, o);
        }
        if (lane == 0) { s_sx[ck] = ux + ax; s_sy[ck] = uy + ay; s_sz[ck] = uz + az; }
    }
    __syncthreads();

    // offset scan (warp 0): exclusive prefix of chunk sums
    if (w == 0) {
        int ck0 = lane * 4;
        float lx[4], ly[4], lz[4];
        float tx = 0.f, ty = 0.f, tz = 0.f;
#pragma unroll
        for (int j = 0; j < 4; ++j) {
            int ck = ck0 + j;
            lx[j] = tx; ly[j] = ty; lz[j] = tz;
            if (ck < NCHUNK) { tx += s_sx[ck]; ty += s_sy[ck]; tz += s_sz[ck]; }
        }
        float ix = tx, iy = ty, iz = tz;
#pragma unroll
        for (int k = 1; k < 32; k <<= 1) {
            float sx = __shfl_up_sync(FULL, ix, k);
            float sy = __shfl_up_sync(FULL, iy, k);
            float sz = __shfl_up_sync(FULL, iz, k);
            if (lane >= k) { ix += sx; iy += sy; iz += sz; }
        }
        float bx = __shfl_up_sync(FULL, ix, 1);
        float by = __shfl_up_sync(FULL, iy, 1);
        float bz = __shfl_up_sync(FULL, iz, 1);
        if (lane == 0) { bx = by = bz = 0.f; }
#pragma unroll
        for (int j = 0; j < 4; ++j) {
            int ck = ck0 + j;
            if (ck < NCHUNK) {
                g_off[(cbase + ck) * 3 + 0] = bx + lx[j];
                g_off[(cbase + ck) * 3 + 1] = by + ly[j];
                g_off[(cbase + ck) * 3 + 2] = bz + lz[j];
            }
        }
    }
}

// ============================================================================
// K3: one chunk per warp, fully warp-independent (NO __syncthreads)
// ============================================================================
__global__ void __launch_bounds__(256)
k3_write(const float* __restrict__ x0, float* __restrict__ out) {
    __shared__ __align__(16) float s_stage[8][CS * 3];
    __shared__ float s_e0sw[8][E0SLEN + 1];     // per-warp e0s copy (slow path only)

    const int b    = blockIdx.x >> 4;
    const int seg  = blockIdx.x & 15;
    const int tid  = threadIdx.x;
    const int w    = tid >> 5;
    const int lane = tid & 31;
    const unsigned FULL = 0xffffffffu;
    const unsigned lemask = FULL >> (31 - lane);
    const int cbase = b * NCHUNK;

    const int ck = seg * 8 + w;
    if (ck >= NCHUNK) return;
    const int gi = cbase + ck;

    // lane-parallel metadata fetch (one round trip), then broadcast
    unsigned mu = 0;
    float    mf = 0.f;
    if (lane == 0)      mu = g_entry[gi];
    else if (lane == 1) mu = g_gmask[gi];
    if (lane == 2)      mf = g_off[gi * 3 + 0];
    else if (lane == 3) mf = g_off[gi * 3 + 1];
    else if (lane == 4) mf = g_off[gi * 3 + 2];
    const unsigned e  = __shfl_sync(FULL, mu, 0);
    const unsigned gm = __shfl_sync(FULL, mu, 1);
    float cx = __shfl_sync(FULL, mf, 2);
    float cy = __shfl_sync(FULL, mf, 3);
    float cz = __shfl_sync(FULL, mf, 4);

    unsigned z = e & 1u;
    int Cin = (int)(e >> 1);
    float4* o4 = reinterpret_cast<float4*>(out + (size_t)(b * NSTEPS + ck * CS) * 3);

    if (gm == 0x1Fu) {
        // all-fast chunk: fetch only the 3 needed e0s floats directly
        int idx = clipIdx(Cin);
        float ev = (lane < 3) ? g_e0s[b * E0SLEN + idx * 3 + lane] : 0.f;
        float spd = z ? 1e-3f : 5e-3f;
        float vx = spd * __shfl_sync(FULL, ev, 0);
        float vy = spd * __shfl_sync(FULL, ev, 1);
        float vz = spd * __shfl_sync(FULL, ev, 2);
#pragma unroll
        for (int i = 0; i < 4; ++i) {
            int idx4 = i * 32 + lane;
            if (idx4 < 120) {
                int f = idx4 * 4;
                float r[4];
#pragma unroll
                for (int k = 0; k < 4; ++k) {
                    int p  = f + k;
                    int t  = p / 3;
                    int cp = p - t * 3;
                    float vv = (cp == 0) ? vx : ((cp == 1) ? vy : vz);
                    float cc = (cp == 0) ? cx : ((cp == 1) ? cy : cz);
                    r[k] = fmaf((float)(t + 1), vv, cc);
                }
                o4[idx4] = make_float4(r[0], r[1], r[2], r[3]);
            }
        }
        return;
    }

    // slow chunk: this warp loads its own e0s copy (warp-local, no block barrier)
    float* se = &s_e0sw[w][0];
    for (int i = lane; i < E0SLEN; i += 32)
        se[i] = g_e0s[b * E0SLEN + i];
    __syncwarp();

    float* st = &s_stage[w][0];
    int sofar = 0;
#pragma unroll
    for (int g = 0; g < NGRP; ++g) {
        int o = (g * 32 + lane) * 3;
        if ((gm >> g) & 1u) {          // fast group: ramp
            float spd = z ? 1e-3f : 5e-3f;
            int idx = clipIdx(Cin + sofar);
            float vx = spd * se[idx * 3 + 0];
            float vy = spd * se[idx * 3 + 1];
            float vz = spd * se[idx * 3 + 2];
            float t = (float)(lane + 1);
            st[o + 0] = fmaf(t, vx, cx);
            st[o + 1] = fmaf(t, vy, cy);
            st[o + 2] = fmaf(t, vz, cz);
            cx = fmaf(32.f, vx, cx);
            cy = fmaf(32.f, vy, cy);
            cz = fmaf(32.f, vz, cz);
            continue;
        }
        uint4 bw = g_ball4[gi * NGRP + g];   // one LDG.128 broadcast
        unsigned wA1 = bw.x, wA2 = bw.y, wB0 = bw.z;
        unsigned Z = affineZ(wA1, wA2, wB0, z);
        unsigned Zp = (Z << 1) | z;
        unsigned S2 = Zp & wA2;
        unsigned S1 = (Zp & wA1) | (~Zp & ~wB0);
        if (ck == 0 && g == 0) S2 &= ~1u;
        int c = Cin + sofar + __popc(S2 & lemask);
        sofar += __popc(S2);
        z = Z >> 31;
        float vx, vy, vz;
        bool tum = (S2 >> lane) & 1u;
        if (ck == 0 && g == 0 && lane == 0) {
            vx = x0[b * 3 + 0]; vy = x0[b * 3 + 1]; vz = x0[b * 3 + 2];
        } else if (tum) {
            vx = vy = vz = 0.f;
        } else {
            float spd = ((S1 >> lane) & 1u) ? 5e-3f : 1e-3f;
            int idx = clipIdx(c);
            vx = spd * se[idx * 3 + 0];
            vy = spd * se[idx * 3 + 1];
            vz = spd * se[idx * 3 + 2];
        }
#pragma unroll
        for (int oo = 1; oo < 32; oo <<= 1) {
            float txu = __shfl_up_sync(FULL, vx, oo);
            float tyu = __shfl_up_sync(FULL, vy, oo);
            float tzu = __shfl_up_sync(FULL, vz, oo);
            if (lane >= oo) { vx += txu; vy += tyu; vz += tzu; }
        }
        st[o + 0] = cx + vx;
        st[o + 1] = cy + vy;
        st[o + 2] = cz + vz;
        cx += __shfl_sync(FULL, vx, 31);
        cy += __shfl_sync(FULL, vy, 31);
        cz += __shfl_sync(FULL, vz, 31);
    }
    __syncwarp();
    const float4* s4 = reinterpret_cast<const float4*>(st);
#pragma unroll
    for (int i = 0; i < 4; ++i) {
        int idx4 = i * 32 + lane;
        if (idx4 < 120) o4[idx4] = s4[idx4];
    }
}

// ---------------- launch ----------------------------------------------------
extern "C" void kernel_launch(void* const* d_in, const int* in_sizes, int n_in,
                              void* d_out, int out_size) {
    const float* x0 = (const float*)d_in[0];
    const float* v0 = (const float*)d_in[1];
    const float* v1 = (const float*)d_in[2];
    const float* r0 = (const float*)d_in[3];
    const float* r1 = (const float*)d_in[4];
    const float* up = (const float*)d_in[5];
    const float* un = (const float*)d_in[6];
    float* X = (float*)d_out;

    k1_ballots<<<K1_WORK_BLOCKS + K1_FRAME_BLOCKS, 256>>>(r0, r1, v0, v1, up, un);
    k2_scan<<<BATCH, 256>>>(x0);
    k3_write<<<K3_BLOCKS, 256>>>(x0, X);
}

// round 12
// speedup vs baseline: 1.0718x; 1.0718x over previous
#include <cuda_runtime.h>
#include <math.h>

#define BATCH   512
#define NSTEPS  20000
#define NTUM    64
#define NCHUNK  125                 // chunks per batch
#define CS      160                 // steps per chunk
#define NGRP    5                   // 32-step groups per chunk
#define NCTOT   (BATCH * NCHUNK)    // 64000 chunks total
#define E0SLEN  ((NTUM + 1) * 3)    // 195 floats per batch

#define K1_WORK_BLOCKS  2000        // 8 warps * 4 chunks = 32 chunks/block
#define K1_FRAME_BLOCKS 64          // 8 warps/block * 64 = 512 frame warps
#define K3_SEGS         16          // 8 chunks per segment (16*8 = 128 >= 125)
#define K3_BLOCKS       (BATCH * K3_SEGS)   // 8192 blocks, 1 chunk per warp

// ---------------- global scratch (L2 resident, ~7 MB) ----------------
__device__ uint4    g_ball4[NCTOT * NGRP];       // ballots (x=wA1,y=wA2,z=wB0)
__device__ unsigned g_cinfo[NCTOT];              // packed chunk maps
__device__ unsigned g_gmask[NCTOT];              // per-group fast bits
__device__ unsigned g_entry[NCTOT];              // z | C<<1
__device__ float    g_off  [NCTOT * 3];          // chunk base positions
__device__ float    g_e0s  [BATCH * E0SLEN];

// ---------------- small vector helpers ----------------
struct F3 { float x, y, z; };
__device__ __forceinline__ F3 mk3(float x, float y, float z) { F3 r{x, y, z}; return r; }
__device__ __forceinline__ float dot3(F3 a, F3 b) { return a.x * b.x + a.y * b.y + a.z * b.z; }
__device__ __forceinline__ F3 cross3(F3 a, F3 b) {
    return mk3(a.y * b.z - a.z * b.y, a.z * b.x - a.x * b.z, a.x * b.y - a.y * b.x);
}
__device__ __forceinline__ F3 nrm3(F3 v) {
    float r = rsqrtf(v.x * v.x + v.y * v.y + v.z * v.z);
    return mk3(v.x * r, v.y * r, v.z * r);
}
__device__ __forceinline__ F3 ortho3(F3 v, F3 u) {
    float k = __fdividef(dot3(v, u), dot3(u, u));
    return mk3(v.x - k * u.x, v.y - k * u.y, v.z - k * u.z);
}
__device__ __forceinline__ float cauchy_angle(float u, float sig) {
    float a = sig * tanf((float)M_PI * (u - 0.5f));   // mu = 0
    if (!isfinite(a)) a = 0.0f;
    return fmodf(a, (float)M_PI);
}
__device__ __forceinline__ void mm3(float* C, const float* A, const float* B) {
#pragma unroll
    for (int i = 0; i < 3; ++i)
#pragma unroll
        for (int j = 0; j < 3; ++j)
            C[3 * i + j] = A[3 * i + 0] * B[j] + A[3 * i + 1] * B[3 + j] +
                           A[3 * i + 2] * B[6 + j];
}

// ---------------- affine GF(2) prefix over 32 steps ----------------------
// Shared Kogge-Stone: P,Q depend only on the ballot words; Z(zin) = Q ^ (zin?P:0)
__device__ __forceinline__ void affinePQ(unsigned wA1, unsigned wA2, unsigned wB0,
                                         unsigned& P, unsigned& Q) {
    unsigned a = ~(wA1 | wA2);
    P = a ^ wB0;
    Q = wB0;
#pragma unroll
    for (int k = 1; k < 32; k <<= 1) {
        Q = Q ^ (P & (Q << k));
        P = P & ((P << k) | ((1u << k) - 1u));
    }
}
__device__ __forceinline__ unsigned affineZ(unsigned wA1, unsigned wA2,
                                            unsigned wB0, unsigned zin) {
    unsigned P, Q;
    affinePQ(wA1, wA2, wB0, P, Q);
    return Q ^ (zin ? P : 0u);
}

__device__ __forceinline__ int clipIdx(int c) {
    int idx = c - 1;
    return idx < 0 ? 0 : (idx > NTUM ? NTUM : idx);
}

// chunk map: bit0=z_out(entry z=1), bit1=z_out(entry z=0),
// [2,17)=cnt(entry=1), [17,32)=cnt(entry=0). Identity = 1.
__device__ __forceinline__ unsigned composeMap(unsigned m1, unsigned m2) {
    unsigned z1 = m1 & 1u;
    unsigned z0 = (m1 >> 1) & 1u;
    unsigned c2a = (m2 >> 2) & 0x7FFFu;
    unsigned c2b = (m2 >> 17) & 0x7FFFu;
    unsigned o1 = z1 ? (m2 & 1u) : ((m2 >> 1) & 1u);
    unsigned o0 = z0 ? (m2 & 1u) : ((m2 >> 1) & 1u);
    unsigned d1 = ((m1 >> 2) & 0x7FFFu) + (z1 ? c2a : c2b);
    unsigned d0 = ((m1 >> 17) & 0x7FFFu) + (z0 ? c2a : c2b);
    return o1 | (o0 << 1) | (d1 << 2) | (d0 << 17);
}

// ============================================================================
// K1: ballots + chunk maps (full-chip parallel) + frame matrix scan
// ============================================================================
__global__ void __launch_bounds__(256)
k1_ballots(const float* __restrict__ r0, const float* __restrict__ r1,
           const float* __restrict__ v0, const float* __restrict__ v1,
           const float* __restrict__ up, const float* __restrict__ un) {
    const int wid  = threadIdx.x >> 5;
    const int lane = threadIdx.x & 31;
    const unsigned FULL = 0xffffffffu;
    const float R01 = 1e-3f, R10 = 1e-3f;
    const float TH  = (float)(1.0 - 1e-3);

    if (blockIdx.x >= K1_WORK_BLOCKS) {
        // -------- frame warps: one batch per warp, matrix prefix scan ------
        int b = (blockIdx.x - K1_WORK_BLOCKS) * 8 + wid;
        if (b >= BATCH) return;
        int i0 = 2 * lane, i1 = 2 * lane + 1;
        float ap0 = cauchy_angle(up[b * NTUM + i0], 0.1f);
        float an0 = cauchy_angle(un[b * NTUM + i0], 0.5f);
        float ap1 = cauchy_angle(up[b * NTUM + i1], 0.1f);
        float an1 = cauchy_angle(un[b * NTUM + i1], 0.5f);
        float cp0 = cosf(ap0), sp0 = sinf(ap0), cb0 = cosf(an0), sb0 = sinf(an0);
        float cp1 = cosf(ap1), sp1 = sinf(ap1), cb1 = cosf(an1), sb1 = sinf(an1);
        float A[9] = { cp0 * cb0, -sp0, cp0 * sb0,
                       sp0 * cb0,  cp0, sp0 * sb0,
                       -sb0,       0.f, cb0 };
        float L1m[9] = { cp1 * cb1, -sp1, cp1 * sb1,
                         sp1 * cb1,  cp1, sp1 * sb1,
                         -sb1,       0.f, cb1 };
        float P[9];
        mm3(P, A, L1m);
#pragma unroll
        for (int k = 1; k < 32; k <<= 1) {
            float U[9];
#pragma unroll
            for (int q = 0; q < 9; ++q) U[q] = __shfl_up_sync(FULL, P[q], k);
            float T[9];
            mm3(T, U, P);
            if (lane >= k) {
#pragma unroll
                for (int q = 0; q < 9; ++q) P[q] = T[q];
            }
        }
        float E[9];
#pragma unroll
        for (int q = 0; q < 9; ++q) E[q] = __shfl_up_sync(FULL, P[q], 1);
        if (lane == 0) {
            E[0] = 1.f; E[1] = 0.f; E[2] = 0.f;
            E[3] = 0.f; E[4] = 1.f; E[5] = 0.f;
            E[6] = 0.f; E[7] = 0.f; E[8] = 1.f;
        }
        F3 a = mk3(v0[b * 3 + 0], v0[b * 3 + 1], v0[b * 3 + 2]);
        F3 c = mk3(v1[b * 3 + 0], v1[b * 3 + 1], v1[b * 3 + 2]);
        F3 e0 = nrm3(a);
        F3 e1 = nrm3(ortho3(c, e0));
        F3 e2 = nrm3(cross3(e0, e1));
        float* eo = &g_e0s[b * E0SLEN];
        if (lane == 0) { eo[0] = e0.x; eo[1] = e0.y; eo[2] = e0.z; }
        float a0x = A[0], a0y = A[3], a0z = A[6];
        float q1x = E[0] * a0x + E[1] * a0y + E[2] * a0z;
        float q1y = E[3] * a0x + E[4] * a0y + E[5] * a0z;
        float q1z = E[6] * a0x + E[7] * a0y + E[8] * a0z;
        int o1 = (2 * lane + 1) * 3;
        eo[o1 + 0] = q1x * e0.x + q1y * e1.x + q1z * e2.x;
        eo[o1 + 1] = q1x * e0.y + q1y * e1.y + q1z * e2.y;
        eo[o1 + 2] = q1x * e0.z + q1y * e1.z + q1z * e2.z;
        float q2x = P[0], q2y = P[3], q2z = P[6];
        int o2 = (2 * lane + 2) * 3;
        eo[o2 + 0] = q2x * e0.x + q2y * e1.x + q2z * e2.x;
        eo[o2 + 1] = q2x * e0.y + q2y * e1.y + q2z * e2.y;
        eo[o2 + 2] = q2x * e0.z + q2y * e1.z + q2z * e2.z;
        return;
    }

    // -------- worker warps: 4 chunks each, batch-agnostic ------------------
    int wgid = blockIdx.x * 8 + wid;          // 0..15999
#pragma unroll
    for (int j = 0; j < 4; ++j) {
        int c = wgid * 4 + j;                 // 0..63999
        int b = c / NCHUNK;
        int ck = c - b * NCHUNK;
        int base = b * NSTEPS + ck * CS;
        // preload ALL group values first -> 10 outstanding LDGs (MLP)
        float a0v[NGRP], a1v[NGRP];
#pragma unroll
        for (int g = 0; g < NGRP; ++g) a0v[g] = r0[base + g * 32 + lane];
#pragma unroll
        for (int g = 0; g < NGRP; ++g) a1v[g] = r1[base + g * 32 + lane];

        unsigned zA = 1u, zB = 0u;
        unsigned cntA = 0, cntB = 0, gmask = 0;
#pragma unroll
        for (int g = 0; g < NGRP; ++g) {
            unsigned wA1 = __ballot_sync(FULL, a0v[g] < R01);
            unsigned wA2 = __ballot_sync(FULL, a0v[g] > TH);
            unsigned wB0 = __ballot_sync(FULL, a1v[g] < R10);
            bool fast = ((wA1 | wA2 | wB0) == 0u) && !(ck == 0 && g == 0);
            if (fast) { gmask |= 1u << g; continue; }
            if (lane == 0)
                g_ball4[c * NGRP + g] = make_uint4(wA1, wA2, wB0, 0u);  // one STG.128
            // shared Kogge-Stone: compute (P,Q) once, derive both entry paths
            unsigned P, Q;
            affinePQ(wA1, wA2, wB0, P, Q);
            unsigned ZA = Q ^ (zA ? P : 0u);
            unsigned ZB = Q ^ (zB ? P : 0u);
            unsigned S2A = ((ZA << 1) | zA) & wA2;
            unsigned S2B = ((ZB << 1) | zB) & wA2;
            if (ck == 0 && g == 0) { S2A &= ~1u; S2B &= ~1u; }
            cntA += __popc(S2A);
            cntB += __popc(S2B);
            zA = ZA >> 31;
            zB = ZB >> 31;
        }
        if (lane == 0) {
            g_cinfo[c] = zA | (zB << 1) | (cntA << 2) | (cntB << 17);
            g_gmask[c] = gmask;
        }
    }
}

// ============================================================================
// K2: per-batch scans + chunk sums -> g_entry, g_off
// ============================================================================
__global__ void __launch_bounds__(256)
k2_scan(const float* __restrict__ x0) {
    __shared__ float    s_e0s[E0SLEN];
    __shared__ unsigned s_entry[NCHUNK];
    __shared__ float    s_sx[NCHUNK], s_sy[NCHUNK], s_sz[NCHUNK];

    const int b    = blockIdx.x;
    const int tid  = threadIdx.x;
    const int w    = tid >> 5;
    const int lane = tid & 31;
    const unsigned FULL = 0xffffffffu;
    const unsigned lemask = FULL >> (31 - lane);
    const int cbase = b * NCHUNK;

    // lane-parallel gmask prefetch: lanes 0..15 load one word each (1 trip)
    const int cs = w * 16;
    const int ce = cs + 16 > NCHUNK ? NCHUNK : cs + 16;
    unsigned gmv = 0x1Fu;
    if (lane < 16 && cs + lane < NCHUNK) gmv = g_gmask[cbase + cs + lane];

    for (int i = tid; i < E0SLEN; i += 256)
        s_e0s[i] = g_e0s[b * E0SLEN + i];

    // scan A (warp 0): chunk entry (z, C)
    if (w == 0) {
        unsigned m = 1u;
        int ck0 = lane * 4;
        unsigned mloc[4];
#pragma unroll
        for (int j = 0; j < 4; ++j) {
            int ck = ck0 + j;
            mloc[j] = (ck < NCHUNK) ? g_cinfo[cbase + ck] : 1u;
            m = composeMap(m, mloc[j]);
        }
#pragma unroll
        for (int k = 1; k < 32; k <<= 1) {
            unsigned mu = __shfl_up_sync(FULL, m, k);
            unsigned mc = composeMap(mu, m);
            if (lane >= k) m = mc;
        }
        unsigned ex = __shfl_up_sync(FULL, m, 1);
        if (lane == 0) ex = 1u;
        unsigned z = ex & 1u;
        unsigned C = (ex >> 2) & 0x7FFFu;
#pragma unroll
        for (int j = 0; j < 4; ++j) {
            int ck = ck0 + j;
            if (ck < NCHUNK) {
                unsigned e = z | (C << 1);
                s_entry[ck] = e;
                g_entry[cbase + ck] = e;
                unsigned mm = mloc[j];
                C += z ? ((mm >> 2) & 0x7FFFu) : ((mm >> 17) & 0x7FFFu);
                z = z ? (mm & 1u) : ((mm >> 1) & 1u);
            }
        }
    }
    __syncthreads();

    // chunk sums: warp w handles [cs, ce)
    for (int jj = 0; jj < 16; ++jj) {
        int ck = cs + jj;
        if (ck >= ce) break;
        unsigned e = s_entry[ck];
        unsigned z = e & 1u;
        int Cin = (int)(e >> 1);
        unsigned gm = __shfl_sync(FULL, gmv, jj);
        if (gm == 0x1Fu) {
            if (lane == 0) {
                float spd = z ? 1e-3f : 5e-3f;
                int idx = clipIdx(Cin);
                s_sx[ck] = CS * spd * s_e0s[idx * 3 + 0];
                s_sy[ck] = CS * spd * s_e0s[idx * 3 + 1];
                s_sz[ck] = CS * spd * s_e0s[idx * 3 + 2];
            }
            continue;
        }
        int sofar = 0;
        float ax = 0.f, ay = 0.f, az = 0.f;
        float ux = 0.f, uy = 0.f, uz = 0.f;
#pragma unroll
        for (int g = 0; g < NGRP; ++g) {
            if ((gm >> g) & 1u) {
                float spd = z ? 1e-3f : 5e-3f;
                int idx = clipIdx(Cin + sofar);
                ux += 32.f * spd * s_e0s[idx * 3 + 0];
                uy += 32.f * spd * s_e0s[idx * 3 + 1];
                uz += 32.f * spd * s_e0s[idx * 3 + 2];
                continue;
            }
            uint4 bw = g_ball4[(cbase + ck) * NGRP + g];   // one LDG.128 broadcast
            unsigned wA1 = bw.x, wA2 = bw.y, wB0 = bw.z;
            unsigned Z = affineZ(wA1, wA2, wB0, z);
            unsigned Zp = (Z << 1) | z;
            unsigned S2 = Zp & wA2;
            unsigned S1 = (Zp & wA1) | (~Zp & ~wB0);
            if (ck == 0 && g == 0) S2 &= ~1u;
            int c = Cin + sofar + __popc(S2 & lemask);
            sofar += __popc(S2);
            z = Z >> 31;
            bool tum = (S2 >> lane) & 1u;
            if (ck == 0 && g == 0 && lane == 0) {
                ax += x0[b * 3 + 0]; ay += x0[b * 3 + 1]; az += x0[b * 3 + 2];
            } else if (!tum) {
                float spd = ((S1 >> lane) & 1u) ? 5e-3f : 1e-3f;
                int idx = clipIdx(c);
                ax += spd * s_e0s[idx * 3 + 0];
                ay += spd * s_e0s[idx * 3 + 1];
                az += spd * s_e0s[idx * 3 + 2];
            }
        }
#pragma unroll
        for (int o = 16; o; o >>= 1) {
            ax += __shfl_xor_sync(FULL, ax, o);
            ay += __shfl_xor_sync(FULL, ay, o);
            az += __shfl_xor_sync(FULL, az, o);
        }
        if (lane == 0) { s_sx[ck] = ux + ax; s_sy[ck] = uy + ay; s_sz[ck] = uz + az; }
    }
    __syncthreads();

    // offset scan (warp 0): exclusive prefix of chunk sums
    if (w == 0) {
        int ck0 = lane * 4;
        float lx[4], ly[4], lz[4];
        float tx = 0.f, ty = 0.f, tz = 0.f;
#pragma unroll
        for (int j = 0; j < 4; ++j) {
            int ck = ck0 + j;
            lx[j] = tx; ly[j] = ty; lz[j] = tz;
            if (ck < NCHUNK) { tx += s_sx[ck]; ty += s_sy[ck]; tz += s_sz[ck]; }
        }
        float ix = tx, iy = ty, iz = tz;
#pragma unroll
        for (int k = 1; k < 32; k <<= 1) {
            float sx = __shfl_up_sync(FULL, ix, k);
            float sy = __shfl_up_sync(FULL, iy, k);
            float sz = __shfl_up_sync(FULL, iz, k);
            if (lane >= k) { ix += sx; iy += sy; iz += sz; }
        }
        float bx = __shfl_up_sync(FULL, ix, 1);
        float by = __shfl_up_sync(FULL, iy, 1);
        float bz = __shfl_up_sync(FULL, iz, 1);
        if (lane == 0) { bx = by = bz = 0.f; }
#pragma unroll
        for (int j = 0; j < 4; ++j) {
            int ck = ck0 + j;
            if (ck < NCHUNK) {
                g_off[(cbase + ck) * 3 + 0] = bx + lx[j];
                g_off[(cbase + ck) * 3 + 1] = by + ly[j];
                g_off[(cbase + ck) * 3 + 2] = bz + lz[j];
            }
        }
    }
}

// ============================================================================
// K3: one chunk per warp, lane-parallel metadata fetch (R10-proven form)
// ============================================================================
__global__ void __launch_bounds__(256)
k3_write(const float* __restrict__ x0, float* __restrict__ out) {
    __shared__ float s_e0s[E0SLEN];
    __shared__ __align__(16) float s_stage[8][CS * 3];

    const int b    = blockIdx.x >> 4;
    const int seg  = blockIdx.x & 15;
    const int tid  = threadIdx.x;
    const int w    = tid >> 5;
    const int lane = tid & 31;
    const unsigned FULL = 0xffffffffu;
    const unsigned lemask = FULL >> (31 - lane);
    const int cbase = b * NCHUNK;

    const int ck = seg * 8 + w;
    const bool valid = ck < NCHUNK;
    const int gi = valid ? (cbase + ck) : cbase;

    // lane-parallel metadata fetch (one round trip), then broadcast
    unsigned mu = 0;
    float    mf = 0.f;
    if (lane == 0)      mu = g_entry[gi];
    else if (lane == 1) mu = g_gmask[gi];
    if (lane == 2)      mf = g_off[gi * 3 + 0];
    else if (lane == 3) mf = g_off[gi * 3 + 1];
    else if (lane == 4) mf = g_off[gi * 3 + 2];
    const unsigned e  = __shfl_sync(FULL, mu, 0);
    const unsigned gm = __shfl_sync(FULL, mu, 1);
    float cx = __shfl_sync(FULL, mf, 2);
    float cy = __shfl_sync(FULL, mf, 3);
    float cz = __shfl_sync(FULL, mf, 4);

    for (int i = tid; i < E0SLEN; i += 256)
        s_e0s[i] = g_e0s[b * E0SLEN + i];
    __syncthreads();
    if (!valid) return;

    unsigned z = e & 1u;
    int Cin = (int)(e >> 1);
    float4* o4 = reinterpret_cast<float4*>(out + (size_t)(b * NSTEPS + ck * CS) * 3);

    if (gm == 0x1Fu) {
        // all-fast chunk: direct ramp stores, scalar regs + SELs (no spill)
        float spd = z ? 1e-3f : 5e-3f;
        int idx = clipIdx(Cin);
        float vx = spd * s_e0s[idx * 3 + 0];
        float vy = spd * s_e0s[idx * 3 + 1];
        float vz = spd * s_e0s[idx * 3 + 2];
#pragma unroll
        for (int i = 0; i < 4; ++i) {
            int idx4 = i * 32 + lane;
            if (idx4 < 120) {
                int f = idx4 * 4;
                float r[4];
#pragma unroll
                for (int k = 0; k < 4; ++k) {
                    int p  = f + k;
                    int t  = p / 3;
                    int cp = p - t * 3;
                    float vv = (cp == 0) ? vx : ((cp == 1) ? vy : vz);
                    float cc = (cp == 0) ? cx : ((cp == 1) ? cy : cz);
                    r[k] = fmaf((float)(t + 1), vv, cc);
                }
                o4[idx4] = make_float4(r[0], r[1], r[2], r[3]);
            }
        }
        return;
    }

    // slow chunk: staged path
    float* st = &s_stage[w][0];
    int sofar = 0;
#pragma unroll
    for (int g = 0; g < NGRP; ++g) {
        int o = (g * 32 + lane) * 3;
        if ((gm >> g) & 1u) {          // fast group: ramp
            float spd = z ? 1e-3f : 5e-3f;
            int idx = clipIdx(Cin + sofar);
            float vx = spd * s_e0s[idx * 3 + 0];
            float vy = spd * s_e0s[idx * 3 + 1];
            float vz = spd * s_e0s[idx * 3 + 2];
            float t = (float)(lane + 1);
            st[o + 0] = fmaf(t, vx, cx);
            st[o + 1] = fmaf(t, vy, cy);
            st[o + 2] = fmaf(t, vz, cz);
            cx = fmaf(32.f, vx, cx);
            cy = fmaf(32.f, vy, cy);
            cz = fmaf(32.f, vz, cz);
            continue;
        }
        uint4 bw = g_ball4[gi * NGRP + g];   // one LDG.128 broadcast
        unsigned wA1 = bw.x, wA2 = bw.y, wB0 = bw.z;
        unsigned Z = affineZ(wA1, wA2, wB0, z);
        unsigned Zp = (Z << 1) | z;
        unsigned S2 = Zp & wA2;
        unsigned S1 = (Zp & wA1) | (~Zp & ~wB0);
        if (ck == 0 && g == 0) S2 &= ~1u;
        int c = Cin + sofar + __popc(S2 & lemask);
        sofar += __popc(S2);
        z = Z >> 31;
        float vx, vy, vz;
        bool tum = (S2 >> lane) & 1u;
        if (ck == 0 && g == 0 && lane == 0) {
            vx = x0[b * 3 + 0]; vy = x0[b * 3 + 1]; vz = x0[b * 3 + 2];
        } else if (tum) {
            vx = vy = vz = 0.f;
        } else {
            float spd = ((S1 >> lane) & 1u) ? 5e-3f : 1e-3f;
            int idx = clipIdx(c);
            vx = spd * s_e0s[idx * 3 + 0];
            vy = spd * s_e0s[idx * 3 + 1];
            vz = spd * s_e0s[idx * 3 + 2];
        }
#pragma unroll
        for (int oo = 1; oo < 32; oo <<= 1) {
            float txu = __shfl_up_sync(FULL, vx, oo);
            float tyu = __shfl_up_sync(FULL, vy, oo);
            float tzu = __shfl_up_sync(FULL, vz, oo);
            if (lane >= oo) { vx += txu; vy += tyu; vz += tzu; }
        }
        st[o + 0] = cx + vx;
        st[o + 1] = cy + vy;
        st[o + 2] = cz + vz;
        cx += __shfl_sync(FULL, vx, 31);
        cy += __shfl_sync(FULL, vy, 31);
        cz += __shfl_sync(FULL, vz, 31);
    }
    __syncwarp();
    const float4* s4 = reinterpret_cast<const float4*>(st);
#pragma unroll
    for (int i = 0; i < 4; ++i) {
        int idx4 = i * 32 + lane;
        if (idx4 < 120) o4[idx4] = s4[idx4];
    }
}

// ---------------- launch ----------------------------------------------------
extern "C" void kernel_launch(void* const* d_in, const int* in_sizes, int n_in,
                              void* d_out, int out_size) {
    const float* x0 = (const float*)d_in[0];
    const float* v0 = (const float*)d_in[1];
    const float* v1 = (const float*)d_in[2];
    const float* r0 = (const float*)d_in[3];
    const float* r1 = (const float*)d_in[4];
    const float* up = (const float*)d_in[5];
    const float* un = (const float*)d_in[6];
    float* X = (float*)d_out;

    k1_ballots<<<K1_WORK_BLOCKS + K1_FRAME_BLOCKS, 256>>>(r0, r1, v0, v1, up, un);
    k2_scan<<<BATCH, 256>>>(x0);
    k3_write<<<K3_BLOCKS, 256>>>(x0, X);
}